// round 12
// baseline (speedup 1.0000x reference)
#include <cuda_runtime.h>
#include <math.h>

#define BATCH 2048
#define TSTEPS 1000
#define NI 40
#define NH 16
#define NR 32
#define NO 2

#define NTILES 32                 // 32-step tiles per batch: 31 full + 1x8
#define NSEG 4
#define SEGB (BATCH / NSEG)       // 512 batches per segment

#define OUT_LOSS 0
#define OUT_D2   1
#define OUT_CORR (1 + (size_t)BATCH * TSTEPS * NO)
#define OUT_TOT  (OUT_CORR + 1)

// 262 MB scratch: pre-scaled dendritic currents cur[b][t][r] (x (1-beta_r))
__device__ __align__(16) float g_cur[(size_t)BATCH * TSTEPS * NR];
// 4 MB scratch: packed spike ballots per 4-batch group per step
__device__ __align__(16) uint2 g_ball[(size_t)(BATCH / 4) * TSTEPS];
// staging for the masked/scaled weights, copied into constant memory
__device__ unsigned long long g_wbuf[NR * 20];
// constant-bank weights: c_w[r*20 + j] = packed f32x2 (w[r][2j], w[r][2j+1])
__constant__ __align__(16) unsigned long long c_w[NR * 20];

__device__ __forceinline__ void fma2(unsigned long long& acc,
                                     unsigned long long a,
                                     unsigned long long b) {
    asm("fma.rn.f32x2 %0, %1, %2, %3;" : "=l"(acc) : "l"(a), "l"(b), "l"(acc));
}
__device__ __forceinline__ unsigned long long packf2(float lo, float hi) {
    unsigned long long r;
    asm("mov.b64 %0, {%1, %2};" : "=l"(r) : "f"(lo), "f"(hi));
    return r;
}
__device__ __forceinline__ void unpackf2(unsigned long long v, float& lo, float& hi) {
    asm("mov.b64 {%0, %1}, %2;" : "=f"(lo), "=f"(hi) : "l"(v));
}
__device__ __forceinline__ float sigm(float v) { return 1.0f / (1.0f + expf(-v)); }

// ---- prep: masked, (1-beta)-scaled, packed weights + output scalar init ----
__global__ void prep_kernel(const float* __restrict__ W1,
                            const float* __restrict__ mask,
                            const float* __restrict__ tau_n,
                            float* __restrict__ out) {
    int r = threadIdx.x;
    if (r == 0) {
        out[OUT_LOSS] = 0.0f;
        int c = 0;
        for (int t = 0; t < TSTEPS; ++t)
            if (t > 10 && ((t - 10) % 15) > 5) c++;
        out[OUT_CORR] = 0.0f;
        out[OUT_TOT] = (float)c * (float)BATCH;
    }
    float om = 1.0f - sigm(tau_n[r]);
    #pragma unroll
    for (int j = 0; j < 20; ++j) {
        int k = 2 * j;
        g_wbuf[r * 20 + j] =
            packf2(W1[r * NI + k]     * mask[r * NI + k]     * om,
                   W1[r * NI + k + 1] * mask[r * NI + k + 1] * om);
    }
}

// ---------------- Kernel A: matvec, one lane per timestep -------------------
__global__ __launch_bounds__(128) void matvec_kernel(
    const float* __restrict__ x, int b0)   // batches [b0, b0+SEGB)
{
    const int wib  = threadIdx.x >> 5;
    const int lane = threadIdx.x & 31;
    const int w    = blockIdx.x * 4 + wib;
    const int b    = b0 + (w >> 5);
    const int tile = w & 31;
    const int t0   = tile * 32;
    const int nsteps = (tile == 31) ? (TSTEPS - 31 * 32) : 32;   // 8 or 32

    __shared__ __align__(16) float sb[4][32 * 44];
    float* sbuf = sb[wib];

    // stage x tile: coalesced GMEM -> padded smem rows
    const float4* xs = reinterpret_cast<const float4*>(
        x + ((size_t)b * TSTEPS + t0) * NI);
    const int nchunk = nsteps * 10;
    #pragma unroll
    for (int i = 0; i < 10; ++i) {
        int c = i * 32 + lane;
        if (c < nchunk) {
            float4 v = xs[c];
            int s = c / 10;
            int q = c - s * 10;
            *reinterpret_cast<float4*>(&sbuf[s * 44 + q * 4]) = v;
        }
    }
    __syncwarp();

    // per-lane read of own step's 160B (conflict-free LDS.128)
    unsigned long long xr[20];
    {
        const ulonglong2* xrow =
            reinterpret_cast<const ulonglong2*>(&sbuf[lane * 44]);
        #pragma unroll
        for (int j2 = 0; j2 < 10; ++j2) {
            ulonglong2 t = xrow[j2];
            xr[2 * j2]     = t.x;
            xr[2 * j2 + 1] = t.y;
        }
    }
    __syncwarp();

    // compute 32 rows; weights via vector (16B) constant loads
    const ulonglong2* cw2 = reinterpret_cast<const ulonglong2*>(c_w);
    #pragma unroll
    for (int rg = 0; rg < 8; ++rg) {
        float4 o;
        #pragma unroll
        for (int rr = 0; rr < 4; ++rr) {
            const int r = rg * 4 + rr;
            unsigned long long acc0 = 0ull, acc1 = 0ull;
            #pragma unroll
            for (int m = 0; m < 10; ++m) {
                ulonglong2 wv = cw2[r * 10 + m];   // LDC.128: 2 weight pairs
                fma2(acc0, wv.x, xr[2 * m]);
                fma2(acc1, wv.y, xr[2 * m + 1]);
            }
            float s0, s1, s2, s3;
            unpackf2(acc0, s0, s1);
            unpackf2(acc1, s2, s3);
            reinterpret_cast<float*>(&o)[rr] = (s0 + s1) + (s2 + s3);
        }
        if (lane < nsteps)
            *reinterpret_cast<float4*>(&sbuf[lane * 44 + rg * 4]) = o;
    }
    __syncwarp();

    // store tile: smem -> coalesced GMEM
    float4* cp = reinterpret_cast<float4*>(
        g_cur + ((size_t)b * TSTEPS + t0) * NR);
    const int ochunk = nsteps * 8;
    #pragma unroll
    for (int i = 0; i < 8; ++i) {
        int c = i * 32 + lane;
        if (c < ochunk) {
            int s = c >> 3;
            int q = c & 7;
            cp[c] = *reinterpret_cast<float4*>(&sbuf[s * 44 + q * 4]);
        }
    }
}

// ---------------- Kernel B: pure state recurrence ---------------------------
#define PD 20

__global__ __launch_bounds__(128) void recur_kernel(
    const float* __restrict__ tau_m,
    const float* __restrict__ tau_n, int b0)
{
    const int lane = threadIdx.x & 31;
    const int lwarp = (blockIdx.x * 128 + threadIdx.x) >> 5;
    const int g    = lane >> 3;
    const int gl   = lane & 7;
    const int b    = b0 + lwarp * 4 + g;
    const int grp  = b0 / 4 + lwarp;           // 4-batch group index
    const unsigned FULL = 0xffffffffu;

    const float4 tn4 = *reinterpret_cast<const float4*>(tau_n + gl * 4);
    const float be0 = sigm(tn4.x), be1 = sigm(tn4.y);
    const float be2 = sigm(tn4.z), be3 = sigm(tn4.w);
    const float2 tm2 = *reinterpret_cast<const float2*>(tau_m + gl * 2);
    const float alA = sigm(tm2.x), omA = 1.0f - alA;
    const float alB = sigm(tm2.y), omB = 1.0f - alB;

    const float4* cp = reinterpret_cast<const float4*>(g_cur)
                     + (size_t)b * TSTEPS * (NR / 4) + gl;
    uint2* bp = g_ball + (size_t)grp * TSTEPS;

    float4 pc[PD];
    #pragma unroll
    for (int j = 0; j < PD; ++j) pc[j] = cp[(size_t)j * (NR / 4)];

    float d0 = 0.f, d1 = 0.f, d2 = 0.f, d3 = 0.f;
    float memA = 0.f, memB = 0.f, spkA = 0.f, spkB = 0.f;

    for (int tt = 0; tt < TSTEPS; tt += PD) {
        #pragma unroll
        for (int u = 0; u < PD; ++u) {
            const int t = tt + u;
            float4 v = pc[u];
            const int tn_ = t + PD;
            if (tn_ < TSTEPS) pc[u] = cp[(size_t)tn_ * (NR / 4)];

            d0 = fmaf(be0, d0, v.x);
            d1 = fmaf(be1, d1, v.y);
            d2 = fmaf(be2, d2, v.z);
            d3 = fmaf(be3, d3, v.w);
            float lA = d0 + d1;
            float lB = d2 + d3;

            memA = fmaf(alA, memA - spkA, omA * lA);
            memB = fmaf(alB, memB - spkB, omB * lB);
            bool sA = memA > 1.0f;               // VTH = 1
            bool sB = memB > 1.0f;
            spkA = sA ? 1.0f : 0.0f;
            spkB = sB ? 1.0f : 0.0f;

            unsigned bA = __ballot_sync(FULL, sA);
            unsigned bB = __ballot_sync(FULL, sB);
            if (lane == 0) bp[t] = make_uint2(bA, bB);
        }
    }
}

// ---------------- Kernel C: parallel logits + CE/accuracy -------------------
#define CBLK 256

__global__ __launch_bounds__(CBLK) void logits_kernel(
    const int*   __restrict__ target,
    const float* __restrict__ W2,
    const float* __restrict__ b2,
    float*       __restrict__ out, int b0)
{
    __shared__ float LA0[256], LA1[256], LB0[256], LB1[256];
    __shared__ float redL[CBLK / 32], redC[CBLK / 32];

    {
        int m = threadIdx.x;
        if (m < 256) {
            float a0 = 0.f, a1 = 0.f, c0 = 0.f, c1 = 0.f;
            #pragma unroll
            for (int gl = 0; gl < 8; ++gl) {
                if ((m >> gl) & 1) {
                    a0 += W2[2 * gl];
                    a1 += W2[NH + 2 * gl];
                    c0 += W2[2 * gl + 1];
                    c1 += W2[NH + 2 * gl + 1];
                }
            }
            LA0[m] = a0; LA1[m] = a1; LB0[m] = c0; LB1[m] = c1;
        }
    }
    __syncthreads();

    const float b20 = b2[0], b21 = b2[1];
    const int i0 = b0 * TSTEPS;
    const int iend = i0 + SEGB * TSTEPS;
    const int stride = gridDim.x * CBLK;

    float lossAcc = 0.0f;
    int   corrAcc = 0;

    for (int i = i0 + blockIdx.x * CBLK + threadIdx.x; i < iend; i += stride) {
        int b = i / TSTEPS;
        int t = i - b * TSTEPS;
        uint2 ball = g_ball[(size_t)(b >> 2) * TSTEPS + t];
        int sh = (b & 3) * 8;
        int a = (ball.x >> sh) & 255;
        int c = (ball.y >> sh) & 255;
        float l0 = b20 + LA0[a] + LB0[c];
        float l1 = b21 + LA1[a] + LB1[c];
        out[OUT_D2 + 2 * (size_t)i]     = l0;
        out[OUT_D2 + 2 * (size_t)i + 1] = l1;

        bool flag = (t > 10) && (((t - 10) % 15) > 5);
        if (flag) {
            int tgt = target[i];
            float z  = l1 - l0;
            float p1 = 1.0f / (1.0f + __expf(-z));
            float p0 = 1.0f - p1;
            float lse = __logf(__expf(p0) + __expf(p1));  // double-softmax CE
            float ptgt = tgt ? p1 : p0;
            lossAcc += (lse - ptgt);
            corrAcc += (((z > 0.0f) ? 1 : 0) == tgt);
        }
    }

    const unsigned FULL = 0xffffffffu;
    float corrF = (float)corrAcc;
    #pragma unroll
    for (int o = 16; o > 0; o >>= 1) {
        lossAcc += __shfl_xor_sync(FULL, lossAcc, o);
        corrF   += __shfl_xor_sync(FULL, corrF, o);
    }
    int wid = threadIdx.x >> 5;
    if ((threadIdx.x & 31) == 0) { redL[wid] = lossAcc; redC[wid] = corrF; }
    __syncthreads();
    if (threadIdx.x == 0) {
        float L = 0.f, C = 0.f;
        #pragma unroll
        for (int k = 0; k < CBLK / 32; ++k) { L += redL[k]; C += redC[k]; }
        atomicAdd(&out[OUT_LOSS], L * (1.0f / (float)BATCH));
        atomicAdd(&out[OUT_CORR], C);
    }
}

extern "C" void kernel_launch(void* const* d_in, const int* in_sizes, int n_in,
                              void* d_out, int out_size) {
    const float* x      = (const float*)d_in[0];
    const int*   target = (const int*)  d_in[1];
    const float* W1     = (const float*)d_in[2];
    const float* tau_m  = (const float*)d_in[3];
    const float* tau_n  = (const float*)d_in[4];
    const float* W2     = (const float*)d_in[6];
    const float* b2     = (const float*)d_in[7];
    const float* mask   = (const float*)d_in[5];
    float* out = (float*)d_out;

    // forked streams + events (host-side objects; fork/join is capture-legal)
    cudaStream_t sR, sL;
    cudaStreamCreateWithFlags(&sR, cudaStreamNonBlocking);
    cudaStreamCreateWithFlags(&sL, cudaStreamNonBlocking);
    cudaEvent_t evM[NSEG], evR[NSEG], evRdone, evLdone;
    for (int s = 0; s < NSEG; ++s) {
        cudaEventCreateWithFlags(&evM[s], cudaEventDisableTiming);
        cudaEventCreateWithFlags(&evR[s], cudaEventDisableTiming);
    }
    cudaEventCreateWithFlags(&evRdone, cudaEventDisableTiming);
    cudaEventCreateWithFlags(&evLdone, cudaEventDisableTiming);

    prep_kernel<<<1, 32, 0, 0>>>(W1, mask, tau_n, out);
    void* wsrc = nullptr;
    cudaGetSymbolAddress(&wsrc, g_wbuf);
    cudaMemcpyToSymbolAsync(c_w, wsrc, sizeof(unsigned long long) * NR * 20,
                            0, cudaMemcpyDeviceToDevice, 0);

    for (int s = 0; s < NSEG; ++s) {
        int b0 = s * SEGB;
        matvec_kernel<<<(SEGB * NTILES) / 4, 128, 0, 0>>>(x, b0);
        cudaEventRecord(evM[s], 0);

        cudaStreamWaitEvent(sR, evM[s], 0);
        recur_kernel<<<(SEGB / 4) / 4, 128, 0, sR>>>(tau_m, tau_n, b0);
        cudaEventRecord(evR[s], sR);

        cudaStreamWaitEvent(sL, evR[s], 0);
        logits_kernel<<<512, CBLK, 0, sL>>>(target, W2, b2, out, b0);
    }

    // join forked streams back into the origin stream
    cudaEventRecord(evRdone, sR);
    cudaEventRecord(evLdone, sL);
    cudaStreamWaitEvent(0, evRdone, 0);
    cudaStreamWaitEvent(0, evLdone, 0);

    for (int s = 0; s < NSEG; ++s) {
        cudaEventDestroy(evM[s]);
        cudaEventDestroy(evR[s]);
    }
    cudaEventDestroy(evRdone);
    cudaEventDestroy(evLdone);
    cudaStreamDestroy(sR);
    cudaStreamDestroy(sL);
}

// round 13
// speedup vs baseline: 1.5048x; 1.5048x over previous
#include <cuda_runtime.h>
#include <math.h>

#define BATCH 2048
#define TSTEPS 1000
#define NI 40
#define NH 16
#define NR 32
#define NO 2

#define NTILES 32                 // 32-step tiles per batch: 31 full + 1x8
#define OUT_LOSS 0
#define OUT_D2   1
#define OUT_CORR (1 + (size_t)BATCH * TSTEPS * NO)
#define OUT_TOT  (OUT_CORR + 1)

// 262 MB scratch: pre-scaled dendritic currents cur[b][t][r] (x (1-beta_r))
__device__ __align__(16) float g_cur[(size_t)BATCH * TSTEPS * NR];
// 4 MB scratch: packed spike ballots per 4-batch group per step
__device__ __align__(16) uint2 g_ball[(size_t)(BATCH / 4) * TSTEPS];
// staging for the masked/scaled weights, copied into constant memory
__device__ unsigned long long g_wbuf[NR * 20];
// constant-bank weights: c_w[r*20 + j] = packed f32x2 (w[r][2j], w[r][2j+1])
__constant__ __align__(16) unsigned long long c_w[NR * 20];

__device__ __forceinline__ void fma2(unsigned long long& acc,
                                     unsigned long long a,
                                     unsigned long long b) {
    asm("fma.rn.f32x2 %0, %1, %2, %3;" : "=l"(acc) : "l"(a), "l"(b), "l"(acc));
}
__device__ __forceinline__ unsigned long long packf2(float lo, float hi) {
    unsigned long long r;
    asm("mov.b64 %0, {%1, %2};" : "=l"(r) : "f"(lo), "f"(hi));
    return r;
}
__device__ __forceinline__ void unpackf2(unsigned long long v, float& lo, float& hi) {
    asm("mov.b64 {%0, %1}, %2;" : "=f"(lo), "=f"(hi) : "l"(v));
}
__device__ __forceinline__ float sigm(float v) { return 1.0f / (1.0f + expf(-v)); }

// ---- prep: masked, (1-beta)-scaled, packed weights + output scalar init ----
__global__ void prep_kernel(const float* __restrict__ W1,
                            const float* __restrict__ mask,
                            const float* __restrict__ tau_n,
                            float* __restrict__ out) {
    int r = threadIdx.x;  // one lane per row
    if (r == 0) {
        out[OUT_LOSS] = 0.0f;
        int c = 0;
        for (int t = 0; t < TSTEPS; ++t)
            if (t > 10 && ((t - 10) % 15) > 5) c++;
        out[OUT_CORR] = 0.0f;
        out[OUT_TOT] = (float)c * (float)BATCH;
    }
    float om = 1.0f - sigm(tau_n[r]);
    #pragma unroll
    for (int j = 0; j < 20; ++j) {
        int k = 2 * j;
        g_wbuf[r * 20 + j] =
            packf2(W1[r * NI + k]     * mask[r * NI + k]     * om,
                   W1[r * NI + k + 1] * mask[r * NI + k + 1] * om);
    }
}

// ---------------- Kernel A: matvec, one lane per timestep -------------------
// warp w: batch b = w/32, tile = w%32 -> steps [32*tile, 32*tile+nsteps).
// Lane s computes cur[b][t0+s][0..31] with weights from the constant bank.
__global__ __launch_bounds__(128) void matvec_kernel(
    const float* __restrict__ x)     // [B, T, NI]
{
    const int wib  = threadIdx.x >> 5;
    const int lane = threadIdx.x & 31;
    const int w    = blockIdx.x * 4 + wib;
    const int b    = w >> 5;
    const int tile = w & 31;
    const int t0   = tile * 32;
    const int nsteps = (tile == 31) ? (TSTEPS - 31 * 32) : 32;   // 8 or 32

    // padded rows: 44 floats (176B) per step -> conflict-free per-lane reads
    __shared__ __align__(16) float sb[4][32 * 44];
    float* sbuf = sb[wib];

    // ---- stage x tile: coalesced GMEM -> transposed smem rows ----
    const float4* xs = reinterpret_cast<const float4*>(
        x + ((size_t)b * TSTEPS + t0) * NI);
    const int nchunk = nsteps * 10;               // 16B chunks in tile
    #pragma unroll
    for (int i = 0; i < 10; ++i) {
        int c = i * 32 + lane;
        if (c < nchunk) {
            float4 v = xs[c];
            int s = c / 10;                        // step row
            int q = c - s * 10;                    // 16B group in row
            *reinterpret_cast<float4*>(&sbuf[s * 44 + q * 4]) = v;
        }
    }
    __syncwarp();

    // ---- per-lane read of own step's 160B (conflict-free LDS.128) ----
    unsigned long long xr[20];
    {
        const ulonglong2* xrow =
            reinterpret_cast<const ulonglong2*>(&sbuf[lane * 44]);
        #pragma unroll
        for (int j2 = 0; j2 < 10; ++j2) {
            ulonglong2 t = xrow[j2];
            xr[2 * j2]     = t.x;
            xr[2 * j2 + 1] = t.y;
        }
    }
    __syncwarp();

    // ---- compute 32 rows; weights via vector (16B) constant loads ----
    const ulonglong2* cw2 = reinterpret_cast<const ulonglong2*>(c_w);
    #pragma unroll
    for (int rg = 0; rg < 8; ++rg) {
        float4 o;
        #pragma unroll
        for (int rr = 0; rr < 4; ++rr) {
            const int r = rg * 4 + rr;
            unsigned long long acc0 = 0ull, acc1 = 0ull;
            #pragma unroll
            for (int m = 0; m < 10; ++m) {
                ulonglong2 wv = cw2[r * 10 + m];   // LDC.128: 2 weight pairs
                fma2(acc0, wv.x, xr[2 * m]);
                fma2(acc1, wv.y, xr[2 * m + 1]);
            }
            float s0, s1, s2, s3;
            unpackf2(acc0, s0, s1);
            unpackf2(acc1, s2, s3);
            reinterpret_cast<float*>(&o)[rr] = (s0 + s1) + (s2 + s3);
        }
        if (lane < nsteps)
            *reinterpret_cast<float4*>(&sbuf[lane * 44 + rg * 4]) = o;
    }
    __syncwarp();

    // ---- store tile: transposed smem -> coalesced GMEM ----
    float4* cp = reinterpret_cast<float4*>(
        g_cur + ((size_t)b * TSTEPS + t0) * NR);
    const int ochunk = nsteps * 8;                // 16B chunks out
    #pragma unroll
    for (int i = 0; i < 8; ++i) {
        int c = i * 32 + lane;
        if (c < ochunk) {
            int s = c >> 3;
            int q = c & 7;
            cp[c] = *reinterpret_cast<float4*>(&sbuf[s * 44 + q * 4]);
        }
    }
}

// ---------------- Kernel B: pure state recurrence ---------------------------
// lane gl (0..7) of each 8-lane group owns rows 4gl..4gl+3 = neurons 2gl,2gl+1
#define PD 20

__global__ __launch_bounds__(128) void recur_kernel(
    const float* __restrict__ tau_m,  // [NH]
    const float* __restrict__ tau_n)  // [NR]
{
    const int lane = threadIdx.x & 31;
    const int warp = (blockIdx.x * 128 + threadIdx.x) >> 5;
    const int g    = lane >> 3;
    const int gl   = lane & 7;
    const int b    = warp * 4 + g;
    const unsigned FULL = 0xffffffffu;

    const float4 tn4 = *reinterpret_cast<const float4*>(tau_n + gl * 4);
    const float be0 = sigm(tn4.x), be1 = sigm(tn4.y);
    const float be2 = sigm(tn4.z), be3 = sigm(tn4.w);
    const float2 tm2 = *reinterpret_cast<const float2*>(tau_m + gl * 2);
    const float alA = sigm(tm2.x), omA = 1.0f - alA;
    const float alB = sigm(tm2.y), omB = 1.0f - alB;

    const float4* cp = reinterpret_cast<const float4*>(g_cur)
                     + (size_t)b * TSTEPS * (NR / 4) + gl;
    uint2* bp = g_ball + (size_t)warp * TSTEPS;

    float4 pc[PD];
    #pragma unroll
    for (int j = 0; j < PD; ++j) pc[j] = cp[(size_t)j * (NR / 4)];

    float d0 = 0.f, d1 = 0.f, d2 = 0.f, d3 = 0.f;
    float memA = 0.f, memB = 0.f, spkA = 0.f, spkB = 0.f;

    for (int tt = 0; tt < TSTEPS; tt += PD) {
        #pragma unroll
        for (int u = 0; u < PD; ++u) {
            const int t = tt + u;
            float4 v = pc[u];
            const int tn_ = t + PD;
            if (tn_ < TSTEPS) pc[u] = cp[(size_t)tn_ * (NR / 4)];

            d0 = fmaf(be0, d0, v.x);
            d1 = fmaf(be1, d1, v.y);
            d2 = fmaf(be2, d2, v.z);
            d3 = fmaf(be3, d3, v.w);
            float lA = d0 + d1;
            float lB = d2 + d3;

            memA = fmaf(alA, memA - spkA, omA * lA);
            memB = fmaf(alB, memB - spkB, omB * lB);
            bool sA = memA > 1.0f;               // VTH = 1
            bool sB = memB > 1.0f;
            spkA = sA ? 1.0f : 0.0f;
            spkB = sB ? 1.0f : 0.0f;

            unsigned bA = __ballot_sync(FULL, sA);
            unsigned bB = __ballot_sync(FULL, sB);
            if (lane == 0) bp[t] = make_uint2(bA, bB);
        }
    }
}

// ---------------- Kernel C: parallel logits + CE/accuracy -------------------
#define CBLK 256

__global__ __launch_bounds__(CBLK) void logits_kernel(
    const int*   __restrict__ target, // [B, T]
    const float* __restrict__ W2,     // [NO, NH]
    const float* __restrict__ b2,     // [NO]
    float*       __restrict__ out)
{
    __shared__ float LA0[256], LA1[256], LB0[256], LB1[256];
    __shared__ float redL[CBLK / 32], redC[CBLK / 32];

    {
        int m = threadIdx.x;
        if (m < 256) {
            float a0 = 0.f, a1 = 0.f, c0 = 0.f, c1 = 0.f;
            #pragma unroll
            for (int gl = 0; gl < 8; ++gl) {
                if ((m >> gl) & 1) {
                    a0 += W2[2 * gl];
                    a1 += W2[NH + 2 * gl];
                    c0 += W2[2 * gl + 1];
                    c1 += W2[NH + 2 * gl + 1];
                }
            }
            LA0[m] = a0; LA1[m] = a1; LB0[m] = c0; LB1[m] = c1;
        }
    }
    __syncthreads();

    const float b20 = b2[0], b21 = b2[1];
    const int total = BATCH * TSTEPS;
    const int stride = gridDim.x * CBLK;

    float lossAcc = 0.0f;
    int   corrAcc = 0;

    for (int i = blockIdx.x * CBLK + threadIdx.x; i < total; i += stride) {
        int b = i / TSTEPS;
        int t = i - b * TSTEPS;
        uint2 ball = g_ball[(size_t)(b >> 2) * TSTEPS + t];
        int sh = (b & 3) * 8;
        int a = (ball.x >> sh) & 255;
        int c = (ball.y >> sh) & 255;
        float l0 = b20 + LA0[a] + LB0[c];
        float l1 = b21 + LA1[a] + LB1[c];
        out[OUT_D2 + 2 * (size_t)i]     = l0;
        out[OUT_D2 + 2 * (size_t)i + 1] = l1;

        bool flag = (t > 10) && (((t - 10) % 15) > 5);
        if (flag) {
            int tgt = target[i];
            float z  = l1 - l0;
            float p1 = 1.0f / (1.0f + __expf(-z));
            float p0 = 1.0f - p1;
            float lse = __logf(__expf(p0) + __expf(p1));  // double-softmax CE
            float ptgt = tgt ? p1 : p0;
            lossAcc += (lse - ptgt);
            corrAcc += (((z > 0.0f) ? 1 : 0) == tgt);
        }
    }

    const unsigned FULL = 0xffffffffu;
    float corrF = (float)corrAcc;
    #pragma unroll
    for (int o = 16; o > 0; o >>= 1) {
        lossAcc += __shfl_xor_sync(FULL, lossAcc, o);
        corrF   += __shfl_xor_sync(FULL, corrF, o);
    }
    int wid = threadIdx.x >> 5;
    if ((threadIdx.x & 31) == 0) { redL[wid] = lossAcc; redC[wid] = corrF; }
    __syncthreads();
    if (threadIdx.x == 0) {
        float L = 0.f, C = 0.f;
        #pragma unroll
        for (int k = 0; k < CBLK / 32; ++k) { L += redL[k]; C += redC[k]; }
        atomicAdd(&out[OUT_LOSS], L * (1.0f / (float)BATCH));
        atomicAdd(&out[OUT_CORR], C);
    }
}

extern "C" void kernel_launch(void* const* d_in, const int* in_sizes, int n_in,
                              void* d_out, int out_size) {
    const float* x      = (const float*)d_in[0];
    const int*   target = (const int*)  d_in[1];
    const float* W1     = (const float*)d_in[2];
    const float* tau_m  = (const float*)d_in[3];
    const float* tau_n  = (const float*)d_in[4];
    const float* mask   = (const float*)d_in[5];
    const float* W2     = (const float*)d_in[6];
    const float* b2     = (const float*)d_in[7];
    float* out = (float*)d_out;

    prep_kernel<<<1, 32>>>(W1, mask, tau_n, out);

    // device-to-device async copy of the packed weights into constant memory
    void* wsrc = nullptr;
    cudaGetSymbolAddress(&wsrc, g_wbuf);
    cudaMemcpyToSymbolAsync(c_w, wsrc, sizeof(unsigned long long) * NR * 20,
                            0, cudaMemcpyDeviceToDevice, 0);

    matvec_kernel<<<(BATCH * NTILES) / 4, 128>>>(x);
    recur_kernel<<<(BATCH / 4) * 32 / 128, 128>>>(tau_m, tau_n);
    logits_kernel<<<1024, CBLK>>>(target, W2, b2, out);
}

// round 15
// speedup vs baseline: 1.5366x; 1.0211x over previous
#include <cuda_runtime.h>
#include <math.h>

#define BATCH 2048
#define TSTEPS 1000
#define NI 40
#define NH 16
#define NR 32
#define NO 2

#define OUT_LOSS 0
#define OUT_D2   1
#define OUT_CORR (1 + (size_t)BATCH * TSTEPS * NO)
#define OUT_TOT  (OUT_CORR + 1)

// 262 MB scratch: pre-scaled dendritic currents cur[b][t][r] (x (1-beta_r))
__device__ __align__(16) float g_cur[(size_t)BATCH * TSTEPS * NR];
// 4 MB scratch: packed spike ballots per 4-batch group per step
__device__ __align__(16) uint2 g_ball[(size_t)(BATCH / 4) * TSTEPS];
// staging for the masked/scaled weights, copied into constant memory
__device__ unsigned long long g_wbuf[NR * 20];
// constant-bank weights: c_w[r*20 + j] = packed f32x2 (w[r][2j], w[r][2j+1])
__constant__ __align__(16) unsigned long long c_w[NR * 20];

__device__ __forceinline__ void fma2(unsigned long long& acc,
                                     unsigned long long a,
                                     unsigned long long b) {
    asm("fma.rn.f32x2 %0, %1, %2, %3;" : "=l"(acc) : "l"(a), "l"(b), "l"(acc));
}
__device__ __forceinline__ unsigned long long packf2(float lo, float hi) {
    unsigned long long r;
    asm("mov.b64 %0, {%1, %2};" : "=l"(r) : "f"(lo), "f"(hi));
    return r;
}
__device__ __forceinline__ void unpackf2(unsigned long long v, float& lo, float& hi) {
    asm("mov.b64 {%0, %1}, %2;" : "=f"(lo), "=f"(hi) : "l"(v));
}
__device__ __forceinline__ float sigm(float v) { return 1.0f / (1.0f + expf(-v)); }

// ---- prep: masked, (1-beta)-scaled, packed weights + output scalar init ----
__global__ void prep_kernel(const float* __restrict__ W1,
                            const float* __restrict__ mask,
                            const float* __restrict__ tau_n,
                            float* __restrict__ out) {
    int r = threadIdx.x;  // one lane per row
    if (r == 0) {
        out[OUT_LOSS] = 0.0f;
        int c = 0;
        for (int t = 0; t < TSTEPS; ++t)
            if (t > 10 && ((t - 10) % 15) > 5) c++;
        out[OUT_CORR] = 0.0f;
        out[OUT_TOT] = (float)c * (float)BATCH;
    }
    float om = 1.0f - sigm(tau_n[r]);
    #pragma unroll
    for (int j = 0; j < 20; ++j) {
        int k = 2 * j;
        g_wbuf[r * 20 + j] =
            packf2(W1[r * NI + k]     * mask[r * NI + k]     * om,
                   W1[r * NI + k + 1] * mask[r * NI + k + 1] * om);
    }
}

// ---------------- Kernel A: matvec, TWO timesteps per lane ------------------
// warp w: batch b = w/16, pair j = w%16 -> tiles j (steps 32j+lane, full) and
// j+16 (steps 32(j+16)+lane; 8 steps for j==15). Each weight LDCU now feeds
// 4 fma2 (two steps x two packed lanes) instead of 2.
__global__ __launch_bounds__(128) void matvec_kernel(
    const float* __restrict__ x)     // [B, T, NI]
{
    const int wib  = threadIdx.x >> 5;
    const int lane = threadIdx.x & 31;
    const int w    = blockIdx.x * 4 + wib;
    const int b    = w >> 4;
    const int jp   = w & 15;
    const int t0A  = jp * 32;
    const int t0B  = (jp + 16) * 32;
    const int nstepsB = (jp == 15) ? (TSTEPS - 31 * 32) : 32;   // 8 or 32

    // two 32x44-float padded tile buffers per warp (conflict-free rows)
    __shared__ __align__(16) float sb[4][2][32 * 44];
    float* sbufA = sb[wib][0];
    float* sbufB = sb[wib][1];

    // ---- stage both tiles: coalesced GMEM -> transposed smem rows ----
    const float4* xsA = reinterpret_cast<const float4*>(
        x + ((size_t)b * TSTEPS + t0A) * NI);
    const float4* xsB = reinterpret_cast<const float4*>(
        x + ((size_t)b * TSTEPS + t0B) * NI);
    const int nchunkB = nstepsB * 10;
    #pragma unroll
    for (int i = 0; i < 10; ++i) {
        int c = i * 32 + lane;                     // < 320 always for A
        {
            float4 v = xsA[c];
            int s = c / 10;
            int q = c - s * 10;
            *reinterpret_cast<float4*>(&sbufA[s * 44 + q * 4]) = v;
        }
        if (c < nchunkB) {
            float4 v = xsB[c];
            int s = c / 10;
            int q = c - s * 10;
            *reinterpret_cast<float4*>(&sbufB[s * 44 + q * 4]) = v;
        }
    }
    __syncwarp();

    // ---- per-lane read of own steps' 160B each (conflict-free LDS.128) ----
    unsigned long long xrA[20], xrB[20];
    {
        const ulonglong2* ra =
            reinterpret_cast<const ulonglong2*>(&sbufA[lane * 44]);
        const ulonglong2* rb =
            reinterpret_cast<const ulonglong2*>(&sbufB[lane * 44]);
        #pragma unroll
        for (int j2 = 0; j2 < 10; ++j2) {
            ulonglong2 ta = ra[j2];
            xrA[2 * j2]     = ta.x;
            xrA[2 * j2 + 1] = ta.y;
            ulonglong2 tb = rb[j2];     // garbage for invalid lanes: discarded
            xrB[2 * j2]     = tb.x;
            xrB[2 * j2 + 1] = tb.y;
        }
    }
    __syncwarp();

    // ---- compute 32 rows for both steps; each weight feeds 4 fma2 ----
    const bool okB = lane < nstepsB;
    #pragma unroll
    for (int rg = 0; rg < 8; ++rg) {
        float4 oA, oB;
        #pragma unroll
        for (int rr = 0; rr < 4; ++rr) {
            const int r = rg * 4 + rr;
            unsigned long long aA0 = 0ull, aA1 = 0ull;
            unsigned long long aB0 = 0ull, aB1 = 0ull;
            #pragma unroll
            for (int j = 0; j < 10; ++j) {
                unsigned long long w1 = c_w[r * 20 + j];       // uniform LDCU
                unsigned long long w2 = c_w[r * 20 + 10 + j];
                fma2(aA0, w1, xrA[j]);
                fma2(aA1, w2, xrA[10 + j]);
                fma2(aB0, w1, xrB[j]);
                fma2(aB1, w2, xrB[10 + j]);
            }
            float s0, s1, s2, s3;
            unpackf2(aA0, s0, s1);
            unpackf2(aA1, s2, s3);
            reinterpret_cast<float*>(&oA)[rr] = (s0 + s1) + (s2 + s3);
            unpackf2(aB0, s0, s1);
            unpackf2(aB1, s2, s3);
            reinterpret_cast<float*>(&oB)[rr] = (s0 + s1) + (s2 + s3);
        }
        *reinterpret_cast<float4*>(&sbufA[lane * 44 + rg * 4]) = oA;
        if (okB)
            *reinterpret_cast<float4*>(&sbufB[lane * 44 + rg * 4]) = oB;
    }
    __syncwarp();

    // ---- store both tiles: transposed smem -> coalesced GMEM ----
    float4* cpA = reinterpret_cast<float4*>(
        g_cur + ((size_t)b * TSTEPS + t0A) * NR);
    float4* cpB = reinterpret_cast<float4*>(
        g_cur + ((size_t)b * TSTEPS + t0B) * NR);
    const int ochunkB = nstepsB * 8;
    #pragma unroll
    for (int i = 0; i < 8; ++i) {
        int c = i * 32 + lane;                     // < 256 always for A
        {
            int s = c >> 3;
            int q = c & 7;
            cpA[c] = *reinterpret_cast<float4*>(&sbufA[s * 44 + q * 4]);
        }
        if (c < ochunkB) {
            int s = c >> 3;
            int q = c & 7;
            cpB[c] = *reinterpret_cast<float4*>(&sbufB[s * 44 + q * 4]);
        }
    }
}

// ---------------- Kernel B: pure state recurrence ---------------------------
// lane gl (0..7) of each 8-lane group owns rows 4gl..4gl+3 = neurons 2gl,2gl+1
#define PD 20

__global__ __launch_bounds__(128) void recur_kernel(
    const float* __restrict__ tau_m,  // [NH]
    const float* __restrict__ tau_n)  // [NR]
{
    const int lane = threadIdx.x & 31;
    const int warp = (blockIdx.x * 128 + threadIdx.x) >> 5;
    const int g    = lane >> 3;
    const int gl   = lane & 7;
    const int b    = warp * 4 + g;
    const unsigned FULL = 0xffffffffu;

    const float4 tn4 = *reinterpret_cast<const float4*>(tau_n + gl * 4);
    const float be0 = sigm(tn4.x), be1 = sigm(tn4.y);
    const float be2 = sigm(tn4.z), be3 = sigm(tn4.w);
    const float2 tm2 = *reinterpret_cast<const float2*>(tau_m + gl * 2);
    const float alA = sigm(tm2.x), omA = 1.0f - alA;
    const float alB = sigm(tm2.y), omB = 1.0f - alB;

    const float4* cp = reinterpret_cast<const float4*>(g_cur)
                     + (size_t)b * TSTEPS * (NR / 4) + gl;
    uint2* bp = g_ball + (size_t)warp * TSTEPS;

    float4 pc[PD];
    #pragma unroll
    for (int j = 0; j < PD; ++j) pc[j] = cp[(size_t)j * (NR / 4)];

    float d0 = 0.f, d1 = 0.f, d2 = 0.f, d3 = 0.f;
    float memA = 0.f, memB = 0.f, spkA = 0.f, spkB = 0.f;

    for (int tt = 0; tt < TSTEPS; tt += PD) {
        #pragma unroll
        for (int u = 0; u < PD; ++u) {
            const int t = tt + u;
            float4 v = pc[u];
            const int tn_ = t + PD;
            if (tn_ < TSTEPS) pc[u] = cp[(size_t)tn_ * (NR / 4)];

            d0 = fmaf(be0, d0, v.x);
            d1 = fmaf(be1, d1, v.y);
            d2 = fmaf(be2, d2, v.z);
            d3 = fmaf(be3, d3, v.w);
            float lA = d0 + d1;
            float lB = d2 + d3;

            memA = fmaf(alA, memA - spkA, omA * lA);
            memB = fmaf(alB, memB - spkB, omB * lB);
            bool sA = memA > 1.0f;               // VTH = 1
            bool sB = memB > 1.0f;
            spkA = sA ? 1.0f : 0.0f;
            spkB = sB ? 1.0f : 0.0f;

            unsigned bA = __ballot_sync(FULL, sA);
            unsigned bB = __ballot_sync(FULL, sB);
            if (lane == 0) bp[t] = make_uint2(bA, bB);
        }
    }
}

// ---------------- Kernel C: parallel logits + CE/accuracy -------------------
#define CBLK 256

__global__ __launch_bounds__(CBLK) void logits_kernel(
    const int*   __restrict__ target, // [B, T]
    const float* __restrict__ W2,     // [NO, NH]
    const float* __restrict__ b2,     // [NO]
    float*       __restrict__ out)
{
    __shared__ float LA0[256], LA1[256], LB0[256], LB1[256];
    __shared__ float redL[CBLK / 32], redC[CBLK / 32];

    {
        int m = threadIdx.x;
        if (m < 256) {
            float a0 = 0.f, a1 = 0.f, c0 = 0.f, c1 = 0.f;
            #pragma unroll
            for (int gl = 0; gl < 8; ++gl) {
                if ((m >> gl) & 1) {
                    a0 += W2[2 * gl];
                    a1 += W2[NH + 2 * gl];
                    c0 += W2[2 * gl + 1];
                    c1 += W2[NH + 2 * gl + 1];
                }
            }
            LA0[m] = a0; LA1[m] = a1; LB0[m] = c0; LB1[m] = c1;
        }
    }
    __syncthreads();

    const float b20 = b2[0], b21 = b2[1];
    const int total = BATCH * TSTEPS;
    const int stride = gridDim.x * CBLK;

    float lossAcc = 0.0f;
    int   corrAcc = 0;

    for (int i = blockIdx.x * CBLK + threadIdx.x; i < total; i += stride) {
        int b = i / TSTEPS;
        int t = i - b * TSTEPS;
        uint2 ball = g_ball[(size_t)(b >> 2) * TSTEPS + t];
        int sh = (b & 3) * 8;
        int a = (ball.x >> sh) & 255;
        int c = (ball.y >> sh) & 255;
        float l0 = b20 + LA0[a] + LB0[c];
        float l1 = b21 + LA1[a] + LB1[c];
        out[OUT_D2 + 2 * (size_t)i]     = l0;
        out[OUT_D2 + 2 * (size_t)i + 1] = l1;

        bool flag = (t > 10) && (((t - 10) % 15) > 5);
        if (flag) {
            int tgt = target[i];
            float z  = l1 - l0;
            float p1 = 1.0f / (1.0f + __expf(-z));
            float p0 = 1.0f - p1;
            float lse = __logf(__expf(p0) + __expf(p1));  // double-softmax CE
            float ptgt = tgt ? p1 : p0;
            lossAcc += (lse - ptgt);
            corrAcc += (((z > 0.0f) ? 1 : 0) == tgt);
        }
    }

    const unsigned FULL = 0xffffffffu;
    float corrF = (float)corrAcc;
    #pragma unroll
    for (int o = 16; o > 0; o >>= 1) {
        lossAcc += __shfl_xor_sync(FULL, lossAcc, o);
        corrF   += __shfl_xor_sync(FULL, corrF, o);
    }
    int wid = threadIdx.x >> 5;
    if ((threadIdx.x & 31) == 0) { redL[wid] = lossAcc; redC[wid] = corrF; }
    __syncthreads();
    if (threadIdx.x == 0) {
        float L = 0.f, C = 0.f;
        #pragma unroll
        for (int k = 0; k < CBLK / 32; ++k) { L += redL[k]; C += redC[k]; }
        atomicAdd(&out[OUT_LOSS], L * (1.0f / (float)BATCH));
        atomicAdd(&out[OUT_CORR], C);
    }
}

extern "C" void kernel_launch(void* const* d_in, const int* in_sizes, int n_in,
                              void* d_out, int out_size) {
    const float* x      = (const float*)d_in[0];
    const int*   target = (const int*)  d_in[1];
    const float* W1     = (const float*)d_in[2];
    const float* tau_m  = (const float*)d_in[3];
    const float* tau_n  = (const float*)d_in[4];
    const float* mask   = (const float*)d_in[5];
    const float* W2     = (const float*)d_in[6];
    const float* b2     = (const float*)d_in[7];
    float* out = (float*)d_out;

    prep_kernel<<<1, 32>>>(W1, mask, tau_n, out);

    // device-to-device async copy of the packed weights into constant memory
    void* wsrc = nullptr;
    cudaGetSymbolAddress(&wsrc, g_wbuf);
    cudaMemcpyToSymbolAsync(c_w, wsrc, sizeof(unsigned long long) * NR * 20,
                            0, cudaMemcpyDeviceToDevice, 0);

    matvec_kernel<<<(BATCH * 16) / 4, 128>>>(x);
    recur_kernel<<<(BATCH / 4) * 32 / 128, 128>>>(tau_m, tau_n);
    logits_kernel<<<1024, CBLK>>>(target, W2, b2, out);
}

// round 16
// speedup vs baseline: 1.5724x; 1.0233x over previous
#include <cuda_runtime.h>
#include <math.h>

#define BATCH 2048
#define TSTEPS 1000
#define NI 40
#define NH 16
#define NR 32
#define NO 2

#define NTILES 32                 // 32-step tiles per batch: 31 full + 1x8
#define OUT_LOSS 0
#define OUT_D2   1
#define OUT_CORR (1 + (size_t)BATCH * TSTEPS * NO)
#define OUT_TOT  (OUT_CORR + 1)

// 262 MB scratch: pre-scaled dendritic currents cur[b][t][r] (x (1-beta_r))
__device__ __align__(16) float g_cur[(size_t)BATCH * TSTEPS * NR];
// 4 MB scratch: packed spike ballots per 4-batch group per step
__device__ __align__(16) uint2 g_ball[(size_t)(BATCH / 4) * TSTEPS];
// staging for the masked/scaled weights, copied into constant memory
__device__ unsigned long long g_wbuf[NR * 20];
// constant-bank weights: c_w[r*20 + j] = packed f32x2 (w[r][2j], w[r][2j+1])
__constant__ __align__(16) unsigned long long c_w[NR * 20];

__device__ __forceinline__ void fma2(unsigned long long& acc,
                                     unsigned long long a,
                                     unsigned long long b) {
    asm("fma.rn.f32x2 %0, %1, %2, %3;" : "=l"(acc) : "l"(a), "l"(b), "l"(acc));
}
__device__ __forceinline__ unsigned long long packf2(float lo, float hi) {
    unsigned long long r;
    asm("mov.b64 %0, {%1, %2};" : "=l"(r) : "f"(lo), "f"(hi));
    return r;
}
__device__ __forceinline__ void unpackf2(unsigned long long v, float& lo, float& hi) {
    asm("mov.b64 {%0, %1}, %2;" : "=f"(lo), "=f"(hi) : "l"(v));
}
__device__ __forceinline__ float sigm(float v) { return 1.0f / (1.0f + expf(-v)); }

// ---- prep: masked, (1-beta)-scaled, packed weights + output scalar init ----
__global__ void prep_kernel(const float* __restrict__ W1,
                            const float* __restrict__ mask,
                            const float* __restrict__ tau_n,
                            float* __restrict__ out) {
    int r = threadIdx.x;  // one lane per row
    if (r == 0) {
        out[OUT_LOSS] = 0.0f;
        int c = 0;
        for (int t = 0; t < TSTEPS; ++t)
            if (t > 10 && ((t - 10) % 15) > 5) c++;
        out[OUT_CORR] = 0.0f;
        out[OUT_TOT] = (float)c * (float)BATCH;
    }
    float om = 1.0f - sigm(tau_n[r]);
    #pragma unroll
    for (int j = 0; j < 20; ++j) {
        int k = 2 * j;
        g_wbuf[r * 20 + j] =
            packf2(W1[r * NI + k]     * mask[r * NI + k]     * om,
                   W1[r * NI + k + 1] * mask[r * NI + k + 1] * om);
    }
}

// ---------------- Kernel A: matvec, one lane per timestep (R11-exact) -------
// warp w: batch b = w/32, tile = w%32 -> steps [32*tile, 32*tile+nsteps).
// Lane s computes cur[b][t0+s][0..31] with weights from the constant bank.
__global__ __launch_bounds__(128) void matvec_kernel(
    const float* __restrict__ x)     // [B, T, NI]
{
    const int wib  = threadIdx.x >> 5;
    const int lane = threadIdx.x & 31;
    const int w    = blockIdx.x * 4 + wib;
    const int b    = w >> 5;
    const int tile = w & 31;
    const int t0   = tile * 32;
    const int nsteps = (tile == 31) ? (TSTEPS - 31 * 32) : 32;   // 8 or 32

    // padded rows: 44 floats (176B) per step -> conflict-free per-lane reads
    __shared__ __align__(16) float sb[4][32 * 44];
    float* sbuf = sb[wib];

    // ---- stage x tile: coalesced GMEM -> transposed smem rows ----
    const float4* xs = reinterpret_cast<const float4*>(
        x + ((size_t)b * TSTEPS + t0) * NI);
    const int nchunk = nsteps * 10;               // 16B chunks in tile
    #pragma unroll
    for (int i = 0; i < 10; ++i) {
        int c = i * 32 + lane;
        if (c < nchunk) {
            float4 v = xs[c];
            int s = c / 10;                        // step row
            int q = c - s * 10;                    // 16B group in row
            *reinterpret_cast<float4*>(&sbuf[s * 44 + q * 4]) = v;
        }
    }
    __syncwarp();

    // ---- per-lane read of own step's 160B (conflict-free LDS.128) ----
    unsigned long long xr[20];
    {
        const ulonglong2* xrow =
            reinterpret_cast<const ulonglong2*>(&sbuf[lane * 44]);
        #pragma unroll
        for (int j2 = 0; j2 < 10; ++j2) {
            ulonglong2 t = xrow[j2];
            xr[2 * j2]     = t.x;
            xr[2 * j2 + 1] = t.y;
        }
    }
    __syncwarp();

    // ---- compute 32 rows; scalar uniform constant loads ----
    #pragma unroll
    for (int rg = 0; rg < 8; ++rg) {
        float4 o;
        #pragma unroll
        for (int rr = 0; rr < 4; ++rr) {
            const int r = rg * 4 + rr;
            unsigned long long acc0 = 0ull, acc1 = 0ull;
            #pragma unroll
            for (int j = 0; j < 10; ++j) {
                fma2(acc0, c_w[r * 20 + j],      xr[j]);
                fma2(acc1, c_w[r * 20 + 10 + j], xr[10 + j]);
            }
            float s0, s1, s2, s3;
            unpackf2(acc0, s0, s1);
            unpackf2(acc1, s2, s3);
            reinterpret_cast<float*>(&o)[rr] = (s0 + s1) + (s2 + s3);
        }
        if (lane < nsteps)
            *reinterpret_cast<float4*>(&sbuf[lane * 44 + rg * 4]) = o;
    }
    __syncwarp();

    // ---- store tile: transposed smem -> coalesced GMEM ----
    float4* cp = reinterpret_cast<float4*>(
        g_cur + ((size_t)b * TSTEPS + t0) * NR);
    const int ochunk = nsteps * 8;                // 16B chunks out
    #pragma unroll
    for (int i = 0; i < 8; ++i) {
        int c = i * 32 + lane;
        if (c < ochunk) {
            int s = c >> 3;
            int q = c & 7;
            cp[c] = *reinterpret_cast<float4*>(&sbuf[s * 44 + q * 4]);
        }
    }
}

// ---------------- Kernel B: pure state recurrence (R11-exact) ---------------
// lane gl (0..7) of each 8-lane group owns rows 4gl..4gl+3 = neurons 2gl,2gl+1
#define PD 20

__global__ __launch_bounds__(128) void recur_kernel(
    const float* __restrict__ tau_m,  // [NH]
    const float* __restrict__ tau_n)  // [NR]
{
    const int lane = threadIdx.x & 31;
    const int warp = (blockIdx.x * 128 + threadIdx.x) >> 5;
    const int g    = lane >> 3;
    const int gl   = lane & 7;
    const int b    = warp * 4 + g;
    const unsigned FULL = 0xffffffffu;

    const float4 tn4 = *reinterpret_cast<const float4*>(tau_n + gl * 4);
    const float be0 = sigm(tn4.x), be1 = sigm(tn4.y);
    const float be2 = sigm(tn4.z), be3 = sigm(tn4.w);
    const float2 tm2 = *reinterpret_cast<const float2*>(tau_m + gl * 2);
    const float alA = sigm(tm2.x), omA = 1.0f - alA;
    const float alB = sigm(tm2.y), omB = 1.0f - alB;

    const float4* cp = reinterpret_cast<const float4*>(g_cur)
                     + (size_t)b * TSTEPS * (NR / 4) + gl;
    uint2* bp = g_ball + (size_t)warp * TSTEPS;

    float4 pc[PD];
    #pragma unroll
    for (int j = 0; j < PD; ++j) pc[j] = cp[(size_t)j * (NR / 4)];

    float d0 = 0.f, d1 = 0.f, d2 = 0.f, d3 = 0.f;
    float memA = 0.f, memB = 0.f, spkA = 0.f, spkB = 0.f;

    for (int tt = 0; tt < TSTEPS; tt += PD) {
        #pragma unroll
        for (int u = 0; u < PD; ++u) {
            const int t = tt + u;
            float4 v = pc[u];
            const int tn_ = t + PD;
            if (tn_ < TSTEPS) pc[u] = cp[(size_t)tn_ * (NR / 4)];

            d0 = fmaf(be0, d0, v.x);
            d1 = fmaf(be1, d1, v.y);
            d2 = fmaf(be2, d2, v.z);
            d3 = fmaf(be3, d3, v.w);
            float lA = d0 + d1;
            float lB = d2 + d3;

            memA = fmaf(alA, memA - spkA, omA * lA);
            memB = fmaf(alB, memB - spkB, omB * lB);
            bool sA = memA > 1.0f;               // VTH = 1
            bool sB = memB > 1.0f;
            spkA = sA ? 1.0f : 0.0f;
            spkB = sB ? 1.0f : 0.0f;

            unsigned bA = __ballot_sync(FULL, sA);
            unsigned bB = __ballot_sync(FULL, sB);
            if (lane == 0) bp[t] = make_uint2(bA, bB);
        }
    }
}

// ---------------- Kernel C: logits + CE, one block per batch ----------------
#define CBLK 256

__global__ __launch_bounds__(CBLK) void logits_kernel(
    const int*   __restrict__ target, // [B, T]
    const float* __restrict__ W2,     // [NO, NH]
    const float* __restrict__ b2,     // [NO]
    float*       __restrict__ out)
{
    __shared__ float LA0[256], LA1[256], LB0[256], LB1[256];
    __shared__ float redL[CBLK / 32], redC[CBLK / 32];

    {
        int m = threadIdx.x;
        if (m < 256) {
            float a0 = 0.f, a1 = 0.f, c0 = 0.f, c1 = 0.f;
            #pragma unroll
            for (int gl = 0; gl < 8; ++gl) {
                if ((m >> gl) & 1) {
                    a0 += W2[2 * gl];
                    a1 += W2[NH + 2 * gl];
                    c0 += W2[2 * gl + 1];
                    c1 += W2[NH + 2 * gl + 1];
                }
            }
            LA0[m] = a0; LA1[m] = a1; LB0[m] = c0; LB1[m] = c1;
        }
    }
    __syncthreads();

    const float b20 = b2[0], b21 = b2[1];
    const int b  = blockIdx.x;                    // one block per batch
    const int sh = (b & 3) * 8;
    const uint2* ballRow = g_ball + (size_t)(b >> 2) * TSTEPS;
    const int*   tgtRow  = target + (size_t)b * TSTEPS;
    float*       d2Row   = out + OUT_D2 + (size_t)b * TSTEPS * 2;

    float lossAcc = 0.0f;
    int   corrAcc = 0;

    for (int t = threadIdx.x; t < TSTEPS; t += CBLK) {
        uint2 ball = ballRow[t];                  // coalesced within block
        int a = (ball.x >> sh) & 255;
        int c = (ball.y >> sh) & 255;
        float l0 = b20 + LA0[a] + LB0[c];
        float l1 = b21 + LA1[a] + LB1[c];
        d2Row[2 * t]     = l0;
        d2Row[2 * t + 1] = l1;

        bool flag = (t > 10) && (((t - 10) % 15) > 5);
        if (flag) {
            int tgt = tgtRow[t];
            float z  = l1 - l0;
            float p1 = 1.0f / (1.0f + __expf(-z));
            float p0 = 1.0f - p1;
            float lse = __logf(__expf(p0) + __expf(p1));  // double-softmax CE
            float ptgt = tgt ? p1 : p0;
            lossAcc += (lse - ptgt);
            corrAcc += (((z > 0.0f) ? 1 : 0) == tgt);
        }
    }

    const unsigned FULL = 0xffffffffu;
    float corrF = (float)corrAcc;
    #pragma unroll
    for (int o = 16; o > 0; o >>= 1) {
        lossAcc += __shfl_xor_sync(FULL, lossAcc, o);
        corrF   += __shfl_xor_sync(FULL, corrF, o);
    }
    int wid = threadIdx.x >> 5;
    if ((threadIdx.x & 31) == 0) { redL[wid] = lossAcc; redC[wid] = corrF; }
    __syncthreads();
    if (threadIdx.x == 0) {
        float L = 0.f, C = 0.f;
        #pragma unroll
        for (int k = 0; k < CBLK / 32; ++k) { L += redL[k]; C += redC[k]; }
        atomicAdd(&out[OUT_LOSS], L * (1.0f / (float)BATCH));
        atomicAdd(&out[OUT_CORR], C);
    }
}

extern "C" void kernel_launch(void* const* d_in, const int* in_sizes, int n_in,
                              void* d_out, int out_size) {
    const float* x      = (const float*)d_in[0];
    const int*   target = (const int*)  d_in[1];
    const float* W1     = (const float*)d_in[2];
    const float* tau_m  = (const float*)d_in[3];
    const float* tau_n  = (const float*)d_in[4];
    const float* mask   = (const float*)d_in[5];
    const float* W2     = (const float*)d_in[6];
    const float* b2     = (const float*)d_in[7];
    float* out = (float*)d_out;

    prep_kernel<<<1, 32>>>(W1, mask, tau_n, out);

    // device-to-device async copy of the packed weights into constant memory
    void* wsrc = nullptr;
    cudaGetSymbolAddress(&wsrc, g_wbuf);
    cudaMemcpyToSymbolAsync(c_w, wsrc, sizeof(unsigned long long) * NR * 20,
                            0, cudaMemcpyDeviceToDevice, 0);

    matvec_kernel<<<(BATCH * NTILES) / 4, 128>>>(x);
    recur_kernel<<<(BATCH / 4) * 32 / 128, 128>>>(tau_m, tau_n);
    logits_kernel<<<BATCH, CBLK>>>(target, W2, b2, out);
}